// round 8
// baseline (speedup 1.0000x reference)
#include <cuda_runtime.h>
#include <math.h>
#include <float.h>

// WaveNet autoregressive generation, sm_103a — round 7: 512 threads, 2 rows.
// R6 structure (coalesced float4 weight LDGs, smem partials, staged biases,
// register skip accumulation) with doubled warp parallelism that does NOT
// deepen per-layer reductions or narrow loads:
//   conv: the two conv matrices split across threads (32jq x 8ks x 2mat)
//   skip: k-split 8 (reduce is once per step in registers -> free)
//   res : 32-way k-split of 2, fully register-prefetched

#define NLAYER 30
#define BB 128
#define VV 256
#define RING_PER_ROW 3069   // 3 * (2^10 - 1) slots, 64 floats each

__device__ float g_ring[(size_t)BB * RING_PER_ROW * 64];  // ~100.6 MB scratch

template<int N>
__device__ __forceinline__ void wload(float4* dst, const float4* __restrict__ Wg,
                                      int s4) {
#pragma unroll
    for (int u = 0; u < N; u++) dst[u] = Wg[(size_t)u * s4];
}

// FMA N k-steps (N%4==0), both rows, weights from a register buffer.
template<int N>
__device__ __forceinline__ void mm_reg(const float* __restrict__ a0,
                                       const float* __restrict__ a1,
                                       const float4* w, float4& o0, float4& o1) {
#pragma unroll
    for (int c2 = 0; c2 < N; c2 += 4) {
        float v0[4], v1[4];
        *(float4*)v0 = *(const float4*)(a0 + c2);
        *(float4*)v1 = *(const float4*)(a1 + c2);
#pragma unroll
        for (int u = 0; u < 4; u++) {
            const float4 wv = w[c2 + u];
            o0.x = fmaf(v0[u], wv.x, o0.x);
            o0.y = fmaf(v0[u], wv.y, o0.y);
            o0.z = fmaf(v0[u], wv.z, o0.z);
            o0.w = fmaf(v0[u], wv.w, o0.w);
            o1.x = fmaf(v1[u], wv.x, o1.x);
            o1.y = fmaf(v1[u], wv.y, o1.y);
            o1.z = fmaf(v1[u], wv.z, o1.z);
            o1.w = fmaf(v1[u], wv.w, o1.w);
        }
    }
}

// FMA N k-steps streaming weights from global (independent LDGs pipeline).
template<int N>
__device__ __forceinline__ void mm_gl(const float* __restrict__ a0,
                                      const float* __restrict__ a1,
                                      const float4* __restrict__ Wg, int s4,
                                      float4& o0, float4& o1) {
#pragma unroll
    for (int c2 = 0; c2 < N; c2 += 4) {
        float v0[4], v1[4];
        *(float4*)v0 = *(const float4*)(a0 + c2);
        *(float4*)v1 = *(const float4*)(a1 + c2);
#pragma unroll
        for (int u = 0; u < 4; u++) {
            const float4 wv = Wg[(size_t)(c2 + u) * s4];
            o0.x = fmaf(v0[u], wv.x, o0.x);
            o0.y = fmaf(v0[u], wv.y, o0.y);
            o0.z = fmaf(v0[u], wv.z, o0.z);
            o0.w = fmaf(v0[u], wv.w, o0.w);
            o1.x = fmaf(v1[u], wv.x, o1.x);
            o1.y = fmaf(v1[u], wv.y, o1.y);
            o1.z = fmaf(v1[u], wv.z, o1.z);
            o1.w = fmaf(v1[u], wv.w, o1.w);
        }
    }
}

__global__ __launch_bounds__(512, 1)
void wavenet_kernel(const int* __restrict__ seed,
                    const float* __restrict__ emb,     // (V, 64)
                    const float* __restrict__ kern,    // (L, 2, 64, 128)
                    const float* __restrict__ cbias,   // (L, 128)
                    const float* __restrict__ rw,      // (L, 64, 64)
                    const float* __restrict__ rb,      // (L, 64)
                    const float* __restrict__ sw,      // (L, 64, 256)
                    const float* __restrict__ sb,      // (L, 256)
                    const float* __restrict__ ow0,     // (256, 256)
                    const float* __restrict__ ob0,     // (256)
                    const float* __restrict__ ow1,     // (256, 256)
                    const float* __restrict__ ob1,     // (256)
                    float* __restrict__ out,
                    int T, long long samp_off, long long logit_off, int mode)
{
    __shared__ __align__(16) float sx[2][64];
    __shared__ __align__(16) float sxl[2][64];
    __shared__ __align__(16) float sg[2][64];
    __shared__ __align__(16) float ssk[2][256];
    __shared__ __align__(16) float sh0[2][256];
    __shared__ __align__(16) float slg[2][256];
    __shared__ __align__(16) float cbs[NLAYER * 128];   // staged conv bias
    __shared__ __align__(16) float ssb[256];            // sum of skip biases
    __shared__ __align__(16) float obs0[256], obs1[256];
    __shared__ __align__(16) float pbuf[4096];          // 16KB partials union
    __shared__ int snidx[2];

    float (*scp)[2][128] = (float(*)[2][128])pbuf;   // [16][2][128] conv
    float (*srp)[2][64]  = (float(*)[2][64])pbuf;    // [32][2][64]  res
    float (*ssp)[2][256] = (float(*)[2][256])pbuf;   // [8][2][256]  skip/head

    const int tid = threadIdx.x;
    const int row0 = blockIdx.x * 2;

    // conv: 32 j-quads x (8 k-splits x 2 matrices)
    const int jqc = tid & 31, csplit = tid >> 5;          // csplit 0..15
    const int cmat = csplit & 1, kbc = (csplit >> 1) * 8; // mat + k-base
    // res: 16 j-quads x 32 k-splits of 2
    const int jqr = tid & 15, ksr = tid >> 4, kbr = ksr * 2;
    // skip: 64 j-quads x 8 k-splits of 8
    const int jqs = tid & 63, kss = tid >> 6, kbs = kss * 8;
    // head: 64 j-quads x 8 k-splits of 32
    const int jqh = jqs, ksh = kss, kbh = kss * 32;
    // combine mappings
    const int r = tid >> 6, c = tid & 63;       // tid<128
    const int rh = tid >> 8, ch = tid & 255;    // 512-wide

    float4 wk[4];   // conv rows kbc..kbc+3 of K[cmat], or head rows kbh..+3
    float4 wr[2];   // res rows kbr..kbr+1 (full prefetch)
    float4 ws[4];   // skip rows kbs..kbs+3, or head rows kbh+4..+7
    float4 oskip0 = {0,0,0,0}, oskip1 = {0,0,0,0};
    float  rpop = 0.f, rbv = 0.f;

    // ---- one-time staging ----
    for (int idx = tid; idx < NLAYER * 128; idx += 512) cbs[idx] = cbias[idx];
    if (tid < 256) {
        float s = 0.f;
#pragma unroll 1
        for (int i = 0; i < NLAYER; i++) s += sb[i * 256 + tid];
        ssb[tid] = s;
        obs0[tid] = ob0[tid];
        obs1[tid] = ob1[tid];
    }
    if (tid < 2) snidx[tid] = seed[row0 + tid];
    // prefetch conv (t=0, layer 0); layer-0 pop at t=0 is zero
    wload<4>(wk, (const float4*)kern + ((size_t)cmat * 64 + kbc) * 32 + jqc, 32);
    __syncthreads();

#pragma unroll 1
    for (int t = 0; t < T; t++) {
        // ---- step head ----
        if (tid < 128) {
            sx[r][c] = emb[(size_t)snidx[r] * 64 + c];
            sxl[r][c] = rpop;
        }
        oskip0.x = oskip0.y = oskip0.z = oskip0.w = 0.f;
        oskip1.x = oskip1.y = oskip1.z = oskip1.w = 0.f;
        __syncthreads();

#pragma unroll 1
        for (int i = 0; i < NLAYER; i++) {
            const int d = 1 << (i % 10);
            const long long off = (long long)(i / 10) * 1023 + (d - 1);

            // ---- Phase A: conv FMA (one matrix per thread: 4 pre + 4 stream)
            //      + ring push + rb load + wr/ws prefetch ----
            {
                const float4* K = (const float4*)kern
                    + ((size_t)(i * 2 + cmat) * 64 + kbc) * 32 + jqc;
                const float* a0 = (cmat ? sx[0] : sxl[0]) + kbc;
                const float* a1 = (cmat ? sx[1] : sxl[1]) + kbc;
                float4 o0 = {0,0,0,0}, o1 = {0,0,0,0};
                mm_reg<4>(a0,     a1,     wk, o0, o1);
                mm_gl<4> (a0 + 4, a1 + 4, K + 4 * 32, 32, o0, o1);
                *(float4*)&scp[csplit][0][4 * jqc] = o0;
                *(float4*)&scp[csplit][1][4 * jqc] = o1;
            }
            if (tid < 128) {
                size_t idx = ((size_t)(row0 + r) * RING_PER_ROW + (size_t)off
                              + (t & (d - 1))) * 64 + c;
                g_ring[idx] = sx[r][c];
                rbv = rb[i * 64 + c];         // consumed in Phase D
            }
            wload<2>(wr, (const float4*)rw + (size_t)i * 64 * 16
                         + (size_t)kbr * 16 + jqr, 16);
            wload<4>(ws, (const float4*)sw + (size_t)i * 64 * 64
                         + (size_t)kbs * 64 + jqs, 64);
            __syncthreads();

            // ---- Phase B: gate + next conv (or head W0) prefetch + next pop ----
            if (i < NLAYER - 1) {
                const float4* KN = (const float4*)kern
                    + ((size_t)((i + 1) * 2 + cmat) * 64 + kbc) * 32 + jqc;
                wload<4>(wk, KN, 32);
                if (tid < 128) {
                    const int d2 = 1 << ((i + 1) % 10);
                    const long long off2 = (long long)((i + 1) / 10) * 1023 + (d2 - 1);
                    size_t idx2 = ((size_t)(row0 + r) * RING_PER_ROW + (size_t)off2
                                   + (t & (d2 - 1))) * 64 + c;
                    rpop = (t >= d2) ? g_ring[idx2] : 0.f;
                }
            } else {
                wload<4>(wk, (const float4*)ow0 + (size_t)kbh * 64 + jqh, 64);
            }
            if (tid < 128) {
                float pt = 0.f, ps = 0.f;
#pragma unroll
                for (int s2 = 0; s2 < 16; s2 += 4) {
                    float e0 = (scp[s2][r][c]   + scp[s2+1][r][c])
                             + (scp[s2+2][r][c] + scp[s2+3][r][c]);
                    float e1 = (scp[s2][r][c+64]   + scp[s2+1][r][c+64])
                             + (scp[s2+2][r][c+64] + scp[s2+3][r][c+64]);
                    pt += e0;
                    ps += e1;
                }
                float ht = pt + cbs[i * 128 + c];
                float hs = ps + cbs[i * 128 + 64 + c];
                float e2 = __expf(2.f * ht);
                float th = 1.f - __fdividef(2.f, e2 + 1.f);
                float sig = __fdividef(1.f, 1.f + __expf(-hs));
                sg[r][c] = th * sig;
            }
            __syncthreads();

            // ---- Phase C: res FMA (2k, full prefetch) + skip FMA (reg accum) --
            {
                float x00 = sg[0][kbr], x01 = sg[0][kbr + 1];
                float x10 = sg[1][kbr], x11 = sg[1][kbr + 1];
                float4 o0, o1;
                o0.x = x00 * wr[0].x + x01 * wr[1].x;
                o0.y = x00 * wr[0].y + x01 * wr[1].y;
                o0.z = x00 * wr[0].z + x01 * wr[1].z;
                o0.w = x00 * wr[0].w + x01 * wr[1].w;
                o1.x = x10 * wr[0].x + x11 * wr[1].x;
                o1.y = x10 * wr[0].y + x11 * wr[1].y;
                o1.z = x10 * wr[0].z + x11 * wr[1].z;
                o1.w = x10 * wr[0].w + x11 * wr[1].w;
                *(float4*)&srp[ksr][0][4 * jqr] = o0;
                *(float4*)&srp[ksr][1][4 * jqr] = o1;
            }
            {
                const float4* SW = (const float4*)sw + (size_t)i * 64 * 64
                                   + (size_t)kbs * 64 + jqs;
                mm_reg<4>(sg[0] + kbs,     sg[1] + kbs,     ws, oskip0, oskip1);
                mm_gl<4> (sg[0] + kbs + 4, sg[1] + kbs + 4, SW + 4 * 64, 64,
                          oskip0, oskip1);
            }
            __syncthreads();

            // ---- Phase D: x combine (tree-32) + stage next sxl ----
            if (tid < 128) {
                float acc = 0.f;
#pragma unroll
                for (int s2 = 0; s2 < 32; s2 += 4)
                    acc += (srp[s2][r][c]   + srp[s2+1][r][c])
                         + (srp[s2+2][r][c] + srp[s2+3][r][c]);
                sx[r][c] += rbv + acc;
                if (i < NLAYER - 1) sxl[r][c] = rpop;
            }
            if (i == NLAYER - 1)
                wload<4>(ws, (const float4*)ow0 + (size_t)(kbh + 4) * 64 + jqh, 64);
            __syncthreads();
        }

        // ---- skip finalize: STS register partials, combine + Σbias + relu ----
        *(float4*)&ssp[kss][0][4 * jqs] = oskip0;
        *(float4*)&ssp[kss][1][4 * jqs] = oskip1;
        __syncthreads();
        {
            float v = ssb[ch];
#pragma unroll
            for (int s2 = 0; s2 < 8; s2 += 4)
                v += (ssp[s2][rh][ch]   + ssp[s2+1][rh][ch])
                   + (ssp[s2+2][rh][ch] + ssp[s2+3][rh][ch]);
            ssk[rh][ch] = fmaxf(v, 0.f);
        }
        __syncthreads();

        // ---- head m0: h0 = relu(skip @ ow0 + ob0), 8 pre + 24 stream ----
        {
            const float4* W = (const float4*)ow0 + (size_t)kbh * 64 + jqh;
            float4 o0 = {0,0,0,0}, o1 = {0,0,0,0};
            mm_reg<4>(ssk[0] + kbh,     ssk[1] + kbh,     wk, o0, o1);
            mm_reg<4>(ssk[0] + kbh + 4, ssk[1] + kbh + 4, ws, o0, o1);
            mm_gl<24>(ssk[0] + kbh + 8, ssk[1] + kbh + 8, W + 8 * 64, 64, o0, o1);
            wload<4>(wk, (const float4*)ow1 + (size_t)kbh * 64 + jqh,       64);
            wload<4>(ws, (const float4*)ow1 + (size_t)(kbh + 4) * 64 + jqh, 64);
            *(float4*)&ssp[ksh][0][4 * jqh] = o0;
            *(float4*)&ssp[ksh][1][4 * jqh] = o1;
        }
        __syncthreads();
        {
            float v = obs0[ch];
#pragma unroll
            for (int s2 = 0; s2 < 8; s2 += 4)
                v += (ssp[s2][rh][ch]   + ssp[s2+1][rh][ch])
                   + (ssp[s2+2][rh][ch] + ssp[s2+3][rh][ch]);
            sh0[rh][ch] = fmaxf(v, 0.f);
        }
        __syncthreads();

        // ---- head m1: logits = h0 @ ow1 + ob1 ----
        {
            const float4* W = (const float4*)ow1 + (size_t)kbh * 64 + jqh;
            float4 o0 = {0,0,0,0}, o1 = {0,0,0,0};
            mm_reg<4>(sh0[0] + kbh,     sh0[1] + kbh,     wk, o0, o1);
            mm_reg<4>(sh0[0] + kbh + 4, sh0[1] + kbh + 4, ws, o0, o1);
            mm_gl<24>(sh0[0] + kbh + 8, sh0[1] + kbh + 8, W + 8 * 64, 64, o0, o1);
            // prefetch (t+1, layer 0) conv weights + layer-0 pop
            wload<4>(wk, (const float4*)kern + ((size_t)cmat * 64 + kbc) * 32 + jqc, 32);
            if (tid < 128)
                rpop = g_ring[((size_t)(row0 + r) * RING_PER_ROW) * 64 + c];
            *(float4*)&ssp[ksh][0][4 * jqh] = o0;
            *(float4*)&ssp[ksh][1][4 * jqh] = o1;
        }
        __syncthreads();
        {
            float v = obs1[ch];
#pragma unroll
            for (int s2 = 0; s2 < 8; s2 += 4)
                v += (ssp[s2][rh][ch]   + ssp[s2+1][rh][ch])
                   + (ssp[s2+2][rh][ch] + ssp[s2+3][rh][ch]);
            slg[rh][ch] = v;
            if (mode & 2)
                out[logit_off + ((size_t)(row0 + rh) * T + t) * VV + ch] = v;
        }
        __syncthreads();

        // ---- argmax per row (first-max tie rule, matches jnp.argmax) ----
        if (tid < 64) {
            int rr = tid >> 5, lane = tid & 31;
            float bv = -FLT_MAX;
            int bi = 0;
#pragma unroll
            for (int jj = 0; jj < 8; jj++) {
                int j = lane + jj * 32;
                float v = slg[rr][j];
                if (v > bv) { bv = v; bi = j; }
            }
#pragma unroll
            for (int o2 = 16; o2 > 0; o2 >>= 1) {
                float ov = __shfl_down_sync(0xffffffffu, bv, o2);
                int   oi = __shfl_down_sync(0xffffffffu, bi, o2);
                if (ov > bv || (ov == bv && oi < bi)) { bv = ov; bi = oi; }
            }
            if (lane == 0) {
                snidx[rr] = bi;
                if (mode & 1) out[samp_off + (size_t)(row0 + rr) * T + t] = (float)bi;
                if (mode & 4) ((int*)out)[(size_t)(row0 + rr) * T + t] = bi;
            }
        }
        __syncthreads();
    }
}

extern "C" void kernel_launch(void* const* d_in, const int* in_sizes, int n_in,
                              void* d_out, int out_size) {
    const int*   seed  = (const int*)d_in[0];
    const float* emb   = (const float*)d_in[1];
    const float* kern  = (const float*)d_in[2];
    const float* cbias = (const float*)d_in[3];
    const float* rw    = (const float*)d_in[4];
    const float* rb    = (const float*)d_in[5];
    const float* sw    = (const float*)d_in[6];
    const float* sb    = (const float*)d_in[7];
    const float* ow0   = (const float*)d_in[8];
    const float* ob0   = (const float*)d_in[9];
    const float* ow1   = (const float*)d_in[10];
    const float* ob1   = (const float*)d_in[11];
    (void)in_sizes; (void)n_in;

    int T, mode;
    long long samp_off = 0, logit_off = 0;
    if (out_size % (BB * (VV + 1)) == 0) {
        T = out_size / (BB * (VV + 1));
        mode = 1 | 2;                       // float samples then logits
        samp_off = 0;
        logit_off = (long long)BB * T;
    } else if (out_size % (BB * VV) == 0) {
        T = out_size / (BB * VV);
        mode = 2;                           // logits only
        logit_off = 0;
    } else {
        T = out_size / BB;
        mode = 4;                           // int32 samples only
    }

    wavenet_kernel<<<BB / 2, 512>>>(seed, emb, kern, cbias, rw, rb, sw, sb,
                                    ow0, ob0, ow1, ob1,
                                    (float*)d_out, T, samp_off, logit_off, mode);
}

// round 9
// speedup vs baseline: 1.0173x; 1.0173x over previous
#include <cuda_runtime.h>
#include <math.h>
#include <float.h>

// WaveNet autoregressive generation, sm_103a — round 8: skip-lag overlap.
// Base = round-6 winner (256 threads, 64 CTAs x 2 rows, coalesced float4
// weight LDGs, smem partials, staged biases, register skip accumulation).
// Change: the skip matmul of layer i-1 (44% of layer FLOPs, off the critical
// path) executes as a second independent FMA/LDG stream inside layer i's conv
// phase, so its latency rides under the conv work instead of sitting exposed
// in its own phase. Layer 29's skip runs once after the loop.

#define NLAYER 30
#define BB 128
#define VV 256
#define RING_PER_ROW 3069   // 3 * (2^10 - 1) slots, 64 floats each

__device__ float g_ring[(size_t)BB * RING_PER_ROW * 64];  // ~100.6 MB scratch

template<int N>
__device__ __forceinline__ void wload(float4* dst, const float4* __restrict__ Wg,
                                      int s4) {
#pragma unroll
    for (int u = 0; u < N; u++) dst[u] = Wg[(size_t)u * s4];
}

// FMA N k-steps (N%4==0), both rows, weights from a register buffer.
template<int N>
__device__ __forceinline__ void mm_reg(const float* __restrict__ a0,
                                       const float* __restrict__ a1,
                                       const float4* w, float4& o0, float4& o1) {
#pragma unroll
    for (int c2 = 0; c2 < N; c2 += 4) {
        float v0[4], v1[4];
        *(float4*)v0 = *(const float4*)(a0 + c2);
        *(float4*)v1 = *(const float4*)(a1 + c2);
#pragma unroll
        for (int u = 0; u < 4; u++) {
            const float4 wv = w[c2 + u];
            o0.x = fmaf(v0[u], wv.x, o0.x);
            o0.y = fmaf(v0[u], wv.y, o0.y);
            o0.z = fmaf(v0[u], wv.z, o0.z);
            o0.w = fmaf(v0[u], wv.w, o0.w);
            o1.x = fmaf(v1[u], wv.x, o1.x);
            o1.y = fmaf(v1[u], wv.y, o1.y);
            o1.z = fmaf(v1[u], wv.z, o1.z);
            o1.w = fmaf(v1[u], wv.w, o1.w);
        }
    }
}

// FMA N k-steps streaming weights from global (independent LDGs pipeline).
template<int N>
__device__ __forceinline__ void mm_gl(const float* __restrict__ a0,
                                      const float* __restrict__ a1,
                                      const float4* __restrict__ Wg, int s4,
                                      float4& o0, float4& o1) {
#pragma unroll
    for (int c2 = 0; c2 < N; c2 += 4) {
        float v0[4], v1[4];
        *(float4*)v0 = *(const float4*)(a0 + c2);
        *(float4*)v1 = *(const float4*)(a1 + c2);
#pragma unroll
        for (int u = 0; u < 4; u++) {
            const float4 wv = Wg[(size_t)(c2 + u) * s4];
            o0.x = fmaf(v0[u], wv.x, o0.x);
            o0.y = fmaf(v0[u], wv.y, o0.y);
            o0.z = fmaf(v0[u], wv.z, o0.z);
            o0.w = fmaf(v0[u], wv.w, o0.w);
            o1.x = fmaf(v1[u], wv.x, o1.x);
            o1.y = fmaf(v1[u], wv.y, o1.y);
            o1.z = fmaf(v1[u], wv.z, o1.z);
            o1.w = fmaf(v1[u], wv.w, o1.w);
        }
    }
}

__global__ __launch_bounds__(256, 1)
void wavenet_kernel(const int* __restrict__ seed,
                    const float* __restrict__ emb,     // (V, 64)
                    const float* __restrict__ kern,    // (L, 2, 64, 128)
                    const float* __restrict__ cbias,   // (L, 128)
                    const float* __restrict__ rw,      // (L, 64, 64)
                    const float* __restrict__ rb,      // (L, 64)
                    const float* __restrict__ sw,      // (L, 64, 256)
                    const float* __restrict__ sb,      // (L, 256)
                    const float* __restrict__ ow0,     // (256, 256)
                    const float* __restrict__ ob0,     // (256)
                    const float* __restrict__ ow1,     // (256, 256)
                    const float* __restrict__ ob1,     // (256)
                    float* __restrict__ out,
                    int T, long long samp_off, long long logit_off, int mode)
{
    __shared__ __align__(16) float sx[2][64];
    __shared__ __align__(16) float sxl[2][64];
    __shared__ __align__(16) float sg[2][64];
    __shared__ __align__(16) float ssk[2][256];
    __shared__ __align__(16) float sh0[2][256];
    __shared__ __align__(16) float slg[2][256];
    __shared__ __align__(16) float cbs[NLAYER * 128];   // staged conv bias
    __shared__ __align__(16) float rbs[NLAYER * 64];    // staged res bias
    __shared__ __align__(16) float ssb[256];            // sum of skip biases
    __shared__ __align__(16) float obs0[256], obs1[256];
    __shared__ __align__(16) float pbuf[2048];          // 8KB partials union
    __shared__ int snidx[2];

    float (*scp)[2][128] = (float(*)[2][128])pbuf;   // [8][2][128] conv
    float (*srp)[2][64]  = (float(*)[2][64])pbuf;    // [16][2][64] res
    float (*ssp)[2][256] = (float(*)[2][256])pbuf;   // [4][2][256] skip/head

    const int tid = threadIdx.x;
    const int row0 = blockIdx.x * 2;

    // lanes = consecutive j-quads (coalesced LDG); k-split across warps
    const int jqc = tid & 31, ksc = tid >> 5, kbc = ksc * 8;   // conv 32jq x 8ks
    const int jqr = tid & 15, ksr = tid >> 4, kbr = ksr * 4;   // res  16jq x 16ks
    const int jqs = tid & 63, kss = tid >> 6, kbs = kss * 16;  // skip 64jq x 4ks
    const int jqh = jqs,      ksh = kss,      kbh = kss * 64;  // head 64jq x 4ks
    const int r = tid >> 6, c = tid & 63;                      // tid<128 combines
    const int ch = tid;                                        // head combine col

    float4 wk[8];   // conv K0[0..3]|K1[4..7] prefetch, or head rows
    float4 wr[4];   // res prefetch
    float4 ws[8];   // skip (lagged) prefetch, or head rows
    float4 oskip0 = {0,0,0,0}, oskip1 = {0,0,0,0};  // skip reg accumulators
    float  rpop = 0.f;

    // ---- one-time staging ----
    for (int idx = tid; idx < NLAYER * 128; idx += 256) cbs[idx] = cbias[idx];
    for (int idx = tid; idx < NLAYER * 64;  idx += 256) rbs[idx] = rb[idx];
    {
        float s = 0.f;
#pragma unroll 1
        for (int i = 0; i < NLAYER; i++) s += sb[i * 256 + tid];
        ssb[tid] = s;
        obs0[tid] = ob0[tid];
        obs1[tid] = ob1[tid];
    }
    if (tid < 2) snidx[tid] = seed[row0 + tid];
    // prefetch conv (t=0, layer 0); layer-0 pop at t=0 is zero
    wload<4>(wk,     (const float4*)kern + (size_t)kbc * 32 + jqc,        32);
    wload<4>(wk + 4, (const float4*)kern + (size_t)(64 + kbc) * 32 + jqc, 32);
    __syncthreads();

#pragma unroll 1
    for (int t = 0; t < T; t++) {
        // ---- step head ----
        if (tid < 128) {
            sx[r][c] = emb[(size_t)snidx[r] * 64 + c];
            sxl[r][c] = rpop;
        }
        oskip0.x = oskip0.y = oskip0.z = oskip0.w = 0.f;
        oskip1.x = oskip1.y = oskip1.z = oskip1.w = 0.f;
        __syncthreads();

#pragma unroll 1
        for (int i = 0; i < NLAYER; i++) {
            const int d = 1 << (i % 10);
            const long long off = (long long)(i / 10) * 1023 + (d - 1);

            // ---- Phase A: conv FMA + lagged skip_{i-1} FMA (two independent
            //      streams) + ring push + wr prefetch ----
            {
                const float4* K0 = (const float4*)kern
                    + (size_t)(i * 2) * 64 * 32 + (size_t)kbc * 32 + jqc;
                const float4* K1 = K0 + 64 * 32;
                float4 o0 = {0,0,0,0}, o1 = {0,0,0,0};
                mm_reg<4>(sxl[0] + kbc,     sxl[1] + kbc,     wk,     o0, o1);
                mm_gl<4> (sxl[0] + kbc + 4, sxl[1] + kbc + 4, K0 + 4 * 32, 32, o0, o1);
                mm_reg<4>(sx[0] + kbc,      sx[1] + kbc,      wk + 4, o0, o1);
                mm_gl<4> (sx[0] + kbc + 4,  sx[1] + kbc + 4,  K1 + 4 * 32, 32, o0, o1);
                if (i > 0) {   // skip of layer i-1: sg still holds gate_{i-1}
                    const float4* SW = (const float4*)sw + (size_t)(i - 1) * 64 * 64
                                       + (size_t)kbs * 64 + jqs;
                    mm_reg<8>(sg[0] + kbs,     sg[1] + kbs,     ws, oskip0, oskip1);
                    mm_gl<8> (sg[0] + kbs + 8, sg[1] + kbs + 8, SW + 8 * 64, 64,
                              oskip0, oskip1);
                }
                *(float4*)&scp[ksc][0][4 * jqc] = o0;
                *(float4*)&scp[ksc][1][4 * jqc] = o1;
            }
            if (tid < 128) {
                size_t idx = ((size_t)(row0 + r) * RING_PER_ROW + (size_t)off
                              + (t & (d - 1))) * 64 + c;
                g_ring[idx] = sx[r][c];
            }
            wload<4>(wr, (const float4*)rw + (size_t)i * 64 * 16
                         + (size_t)kbr * 16 + jqr, 16);
            __syncthreads();

            // ---- Phase B: gate + next conv (or head W0) prefetch + next pop ----
            if (i < NLAYER - 1) {
                const float4* KN = (const float4*)kern + (size_t)((i + 1) * 2) * 64 * 32;
                wload<4>(wk,     KN + (size_t)kbc * 32 + jqc,        32);
                wload<4>(wk + 4, KN + (size_t)(64 + kbc) * 32 + jqc, 32);
                if (tid < 128) {
                    const int d2 = 1 << ((i + 1) % 10);
                    const long long off2 = (long long)((i + 1) / 10) * 1023 + (d2 - 1);
                    size_t idx2 = ((size_t)(row0 + r) * RING_PER_ROW + (size_t)off2
                                   + (t & (d2 - 1))) * 64 + c;
                    rpop = (t >= d2) ? g_ring[idx2] : 0.f;
                }
            } else {
                wload<8>(wk, (const float4*)ow0 + (size_t)kbh * 64 + jqh, 64);
            }
            if (tid < 128) {
                float p0 = scp[0][r][c], p1 = scp[1][r][c];
                float p2 = scp[2][r][c], p3 = scp[3][r][c];
                float p4 = scp[4][r][c], p5 = scp[5][r][c];
                float p6 = scp[6][r][c], p7 = scp[7][r][c];
                float q0 = scp[0][r][c+64], q1 = scp[1][r][c+64];
                float q2 = scp[2][r][c+64], q3 = scp[3][r][c+64];
                float q4 = scp[4][r][c+64], q5 = scp[5][r][c+64];
                float q6 = scp[6][r][c+64], q7 = scp[7][r][c+64];
                float ht = (((p0+p1)+(p2+p3)) + ((p4+p5)+(p6+p7))) + cbs[i*128 + c];
                float hs = (((q0+q1)+(q2+q3)) + ((q4+q5)+(q6+q7))) + cbs[i*128 + 64 + c];
                float e2 = __expf(2.f * ht);
                float th = 1.f - __fdividef(2.f, e2 + 1.f);
                float sig = __fdividef(1.f, 1.f + __expf(-hs));
                sg[r][c] = th * sig;
            }
            __syncthreads();

            // ---- Phase C: res FMA (prefetched) + ws prefetch for skip_i lag ----
            {
                float4 o0 = {0,0,0,0}, o1 = {0,0,0,0};
                mm_reg<4>(sg[0] + kbr, sg[1] + kbr, wr, o0, o1);
                *(float4*)&srp[ksr][0][4 * jqr] = o0;
                *(float4*)&srp[ksr][1][4 * jqr] = o1;
            }
            wload<8>(ws, (const float4*)sw + (size_t)i * 64 * 64
                         + (size_t)kbs * 64 + jqs, 64);
            __syncthreads();

            // ---- Phase D: x combine (tree-16) + stage next sxl ----
            if (tid < 128) {
                float a0 = srp[0][r][c] + srp[1][r][c];
                float a1 = srp[2][r][c] + srp[3][r][c];
                float a2 = srp[4][r][c] + srp[5][r][c];
                float a3 = srp[6][r][c] + srp[7][r][c];
                float a4 = srp[8][r][c] + srp[9][r][c];
                float a5 = srp[10][r][c] + srp[11][r][c];
                float a6 = srp[12][r][c] + srp[13][r][c];
                float a7 = srp[14][r][c] + srp[15][r][c];
                float v = sx[r][c] + rbs[i*64 + c]
                        + (((a0+a1)+(a2+a3)) + ((a4+a5)+(a6+a7)));
                sx[r][c] = v;
                if (i < NLAYER - 1) sxl[r][c] = rpop;
            }
            __syncthreads();
        }

        // ---- post-loop: skip of layer 29 (ws prefetched in C_29) ----
        {
            const float4* SW = (const float4*)sw + (size_t)(NLAYER - 1) * 64 * 64
                               + (size_t)kbs * 64 + jqs;
            mm_reg<8>(sg[0] + kbs,     sg[1] + kbs,     ws, oskip0, oskip1);
            mm_gl<8> (sg[0] + kbs + 8, sg[1] + kbs + 8, SW + 8 * 64, 64,
                      oskip0, oskip1);
        }
        // skip finalize: STS register partials; stage ow0 second half into ws
        *(float4*)&ssp[kss][0][4 * jqs] = oskip0;
        *(float4*)&ssp[kss][1][4 * jqs] = oskip1;
        wload<8>(ws, (const float4*)ow0 + (size_t)(kbh + 8) * 64 + jqh, 64);
        __syncthreads();
        // combine + Σbias + relu (256 threads x 2 rows)
        {
            float v0 = ssb[ch] + ((ssp[0][0][ch] + ssp[1][0][ch])
                                + (ssp[2][0][ch] + ssp[3][0][ch]));
            float v1 = ssb[ch] + ((ssp[0][1][ch] + ssp[1][1][ch])
                                + (ssp[2][1][ch] + ssp[3][1][ch]));
            ssk[0][ch] = fmaxf(v0, 0.f);
            ssk[1][ch] = fmaxf(v1, 0.f);
        }
        __syncthreads();

        // ---- head m0: h0 = relu(skip @ ow0 + ob0), 16 pre + 48 stream ----
        {
            const float4* W = (const float4*)ow0 + (size_t)kbh * 64 + jqh;
            float4 o0 = {0,0,0,0}, o1 = {0,0,0,0};
            mm_reg<8>(ssk[0] + kbh,      ssk[1] + kbh,      wk, o0, o1);
            mm_reg<8>(ssk[0] + kbh + 8,  ssk[1] + kbh + 8,  ws, o0, o1);
            mm_gl<48>(ssk[0] + kbh + 16, ssk[1] + kbh + 16, W + 16 * 64, 64, o0, o1);
            wload<8>(wk, (const float4*)ow1 + (size_t)kbh * 64 + jqh,       64);
            wload<8>(ws, (const float4*)ow1 + (size_t)(kbh + 8) * 64 + jqh, 64);
            *(float4*)&ssp[ksh][0][4 * jqh] = o0;
            *(float4*)&ssp[ksh][1][4 * jqh] = o1;
        }
        __syncthreads();
        {
            float v0 = obs0[ch] + ((ssp[0][0][ch] + ssp[1][0][ch])
                                 + (ssp[2][0][ch] + ssp[3][0][ch]));
            float v1 = obs0[ch] + ((ssp[0][1][ch] + ssp[1][1][ch])
                                 + (ssp[2][1][ch] + ssp[3][1][ch]));
            sh0[0][ch] = fmaxf(v0, 0.f);
            sh0[1][ch] = fmaxf(v1, 0.f);
        }
        __syncthreads();

        // ---- head m1: logits = h0 @ ow1 + ob1 ----
        {
            const float4* W = (const float4*)ow1 + (size_t)kbh * 64 + jqh;
            float4 o0 = {0,0,0,0}, o1 = {0,0,0,0};
            mm_reg<8>(sh0[0] + kbh,      sh0[1] + kbh,      wk, o0, o1);
            mm_reg<8>(sh0[0] + kbh + 8,  sh0[1] + kbh + 8,  ws, o0, o1);
            mm_gl<48>(sh0[0] + kbh + 16, sh0[1] + kbh + 16, W + 16 * 64, 64, o0, o1);
            // prefetch (t+1, layer 0) conv weights + layer-0 pop
            wload<4>(wk,     (const float4*)kern + (size_t)kbc * 32 + jqc,        32);
            wload<4>(wk + 4, (const float4*)kern + (size_t)(64 + kbc) * 32 + jqc, 32);
            if (tid < 128)
                rpop = g_ring[((size_t)(row0 + r) * RING_PER_ROW) * 64 + c];
            *(float4*)&ssp[ksh][0][4 * jqh] = o0;
            *(float4*)&ssp[ksh][1][4 * jqh] = o1;
        }
        __syncthreads();
        {
            float v0 = obs1[ch] + ((ssp[0][0][ch] + ssp[1][0][ch])
                                 + (ssp[2][0][ch] + ssp[3][0][ch]));
            float v1 = obs1[ch] + ((ssp[0][1][ch] + ssp[1][1][ch])
                                 + (ssp[2][1][ch] + ssp[3][1][ch]));
            slg[0][ch] = v0;
            slg[1][ch] = v1;
            if (mode & 2) {
                out[logit_off + ((size_t)(row0 + 0) * T + t) * VV + ch] = v0;
                out[logit_off + ((size_t)(row0 + 1) * T + t) * VV + ch] = v1;
            }
        }
        __syncthreads();

        // ---- argmax per row (first-max tie rule, matches jnp.argmax) ----
        if (tid < 64) {
            int rr = tid >> 5, lane = tid & 31;
            float bv = -FLT_MAX;
            int bi = 0;
#pragma unroll
            for (int jj = 0; jj < 8; jj++) {
                int j = lane + jj * 32;
                float v = slg[rr][j];
                if (v > bv) { bv = v; bi = j; }
            }
#pragma unroll
            for (int o2 = 16; o2 > 0; o2 >>= 1) {
                float ov = __shfl_down_sync(0xffffffffu, bv, o2);
                int   oi = __shfl_down_sync(0xffffffffu, bi, o2);
                if (ov > bv || (ov == bv && oi < bi)) { bv = ov; bi = oi; }
            }
            if (lane == 0) {
                snidx[rr] = bi;
                if (mode & 1) out[samp_off + (size_t)(row0 + rr) * T + t] = (float)bi;
                if (mode & 4) ((int*)out)[(size_t)(row0 + rr) * T + t] = bi;
            }
        }
        __syncthreads();
    }
}

extern "C" void kernel_launch(void* const* d_in, const int* in_sizes, int n_in,
                              void* d_out, int out_size) {
    const int*   seed  = (const int*)d_in[0];
    const float* emb   = (const float*)d_in[1];
    const float* kern  = (const float*)d_in[2];
    const float* cbias = (const float*)d_in[3];
    const float* rw    = (const float*)d_in[4];
    const float* rb    = (const float*)d_in[5];
    const float* sw    = (const float*)d_in[6];
    const float* sb    = (const float*)d_in[7];
    const float* ow0   = (const float*)d_in[8];
    const float* ob0   = (const float*)d_in[9];
    const float* ow1   = (const float*)d_in[10];
    const float* ob1   = (const float*)d_in[11];
    (void)in_sizes; (void)n_in;

    int T, mode;
    long long samp_off = 0, logit_off = 0;
    if (out_size % (BB * (VV + 1)) == 0) {
        T = out_size / (BB * (VV + 1));
        mode = 1 | 2;                       // float samples then logits
        samp_off = 0;
        logit_off = (long long)BB * T;
    } else if (out_size % (BB * VV) == 0) {
        T = out_size / (BB * VV);
        mode = 2;                           // logits only
        logit_off = 0;
    } else {
        T = out_size / BB;
        mode = 4;                           // int32 samples only
    }

    wavenet_kernel<<<BB / 2, 256>>>(seed, emb, kern, cbias, rw, rb, sw, sb,
                                    ow0, ob0, ow1, ob1,
                                    (float*)d_out, T, samp_off, logit_off, mode);
}

// round 10
// speedup vs baseline: 1.0848x; 1.0664x over previous
#include <cuda_runtime.h>
#include <math.h>
#include <float.h>

// WaveNet autoregressive generation, sm_103a — round 9.
// Base = round-6 winner (256 threads, 64 CTAs x 2 rows, coalesced float4
// weight LDGs, smem partials, staged biases, register skip accumulation).
// Change vs R6: same 80 weight-prefetch registers, reallocated. Conv is FULLY
// register-prefetched (16 float4, loaded one phase ahead) so Phase A has zero
// exposed LDG latency; skip is fully streamed in Phase C where the freed
// registers let ptxas batch the LDGs under the prefetched res FMAs.

#define NLAYER 30
#define BB 128
#define VV 256
#define RING_PER_ROW 3069   // 3 * (2^10 - 1) slots, 64 floats each

__device__ float g_ring[(size_t)BB * RING_PER_ROW * 64];  // ~100.6 MB scratch

template<int N>
__device__ __forceinline__ void wload(float4* dst, const float4* __restrict__ Wg,
                                      int s4) {
#pragma unroll
    for (int u = 0; u < N; u++) dst[u] = Wg[(size_t)u * s4];
}

// FMA N k-steps (N%4==0), both rows, weights from a register buffer.
template<int N>
__device__ __forceinline__ void mm_reg(const float* __restrict__ a0,
                                       const float* __restrict__ a1,
                                       const float4* w, float4& o0, float4& o1) {
#pragma unroll
    for (int c2 = 0; c2 < N; c2 += 4) {
        float v0[4], v1[4];
        *(float4*)v0 = *(const float4*)(a0 + c2);
        *(float4*)v1 = *(const float4*)(a1 + c2);
#pragma unroll
        for (int u = 0; u < 4; u++) {
            const float4 wv = w[c2 + u];
            o0.x = fmaf(v0[u], wv.x, o0.x);
            o0.y = fmaf(v0[u], wv.y, o0.y);
            o0.z = fmaf(v0[u], wv.z, o0.z);
            o0.w = fmaf(v0[u], wv.w, o0.w);
            o1.x = fmaf(v1[u], wv.x, o1.x);
            o1.y = fmaf(v1[u], wv.y, o1.y);
            o1.z = fmaf(v1[u], wv.z, o1.z);
            o1.w = fmaf(v1[u], wv.w, o1.w);
        }
    }
}

// FMA N k-steps streaming weights from global (independent LDGs pipeline).
template<int N>
__device__ __forceinline__ void mm_gl(const float* __restrict__ a0,
                                      const float* __restrict__ a1,
                                      const float4* __restrict__ Wg, int s4,
                                      float4& o0, float4& o1) {
#pragma unroll
    for (int c2 = 0; c2 < N; c2 += 4) {
        float v0[4], v1[4];
        *(float4*)v0 = *(const float4*)(a0 + c2);
        *(float4*)v1 = *(const float4*)(a1 + c2);
#pragma unroll
        for (int u = 0; u < 4; u++) {
            const float4 wv = Wg[(size_t)(c2 + u) * s4];
            o0.x = fmaf(v0[u], wv.x, o0.x);
            o0.y = fmaf(v0[u], wv.y, o0.y);
            o0.z = fmaf(v0[u], wv.z, o0.z);
            o0.w = fmaf(v0[u], wv.w, o0.w);
            o1.x = fmaf(v1[u], wv.x, o1.x);
            o1.y = fmaf(v1[u], wv.y, o1.y);
            o1.z = fmaf(v1[u], wv.z, o1.z);
            o1.w = fmaf(v1[u], wv.w, o1.w);
        }
    }
}

__global__ __launch_bounds__(256, 1)
void wavenet_kernel(const int* __restrict__ seed,
                    const float* __restrict__ emb,     // (V, 64)
                    const float* __restrict__ kern,    // (L, 2, 64, 128)
                    const float* __restrict__ cbias,   // (L, 128)
                    const float* __restrict__ rw,      // (L, 64, 64)
                    const float* __restrict__ rb,      // (L, 64)
                    const float* __restrict__ sw,      // (L, 64, 256)
                    const float* __restrict__ sb,      // (L, 256)
                    const float* __restrict__ ow0,     // (256, 256)
                    const float* __restrict__ ob0,     // (256)
                    const float* __restrict__ ow1,     // (256, 256)
                    const float* __restrict__ ob1,     // (256)
                    float* __restrict__ out,
                    int T, long long samp_off, long long logit_off, int mode)
{
    __shared__ __align__(16) float sx[2][64];
    __shared__ __align__(16) float sxl[2][64];
    __shared__ __align__(16) float sg[2][64];
    __shared__ __align__(16) float ssk[2][256];
    __shared__ __align__(16) float sh0[2][256];
    __shared__ __align__(16) float slg[2][256];
    __shared__ __align__(16) float cbs[NLAYER * 128];   // staged conv bias
    __shared__ __align__(16) float rbs[NLAYER * 64];    // staged res bias
    __shared__ __align__(16) float ssb[256];            // sum of skip biases
    __shared__ __align__(16) float obs0[256], obs1[256];
    __shared__ __align__(16) float pbuf[2048];           // 8KB partials union
    __shared__ int snidx[2];

    float (*scp)[2][128] = (float(*)[2][128])pbuf;   // [8][2][128] conv
    float (*srp)[2][64]  = (float(*)[2][64])pbuf;    // [16][2][64] res
    float (*ssp)[2][256] = (float(*)[2][256])pbuf;   // [4][2][256] skip/head

    const int tid = threadIdx.x;
    const int row0 = blockIdx.x * 2;

    // lanes = consecutive j-quads (coalesced LDG); k-split across warps
    const int jqc = tid & 31, ksc = tid >> 5, kbc = ksc * 8;   // conv 32jq x 8ks
    const int jqr = tid & 15, ksr = tid >> 4, kbr = ksr * 4;   // res  16jq x 16ks
    const int jqs = tid & 63, kss = tid >> 6, kbs = kss * 16;  // skip 64jq x 4ks
    const int jqh = jqs,      ksh = kss,      kbh = kss * 64;  // head 64jq x 4ks
    const int r = tid >> 6, c = tid & 63;                      // tid<128 combines
    const int ch = tid;                                        // head combine col

    float4 wk[16];  // conv K0[0..7]|K1[8..15] full prefetch, or head rows
    float4 wr[4];   // res prefetch
    float4 oskip0 = {0,0,0,0}, oskip1 = {0,0,0,0};  // skip reg accumulators
    float  rpop = 0.f;

    // ---- one-time staging ----
    for (int idx = tid; idx < NLAYER * 128; idx += 256) cbs[idx] = cbias[idx];
    for (int idx = tid; idx < NLAYER * 64;  idx += 256) rbs[idx] = rb[idx];
    {
        float s = 0.f;
#pragma unroll 1
        for (int i = 0; i < NLAYER; i++) s += sb[i * 256 + tid];
        ssb[tid] = s;
        obs0[tid] = ob0[tid];
        obs1[tid] = ob1[tid];
    }
    if (tid < 2) snidx[tid] = seed[row0 + tid];
    // prefetch conv (t=0, layer 0); layer-0 pop at t=0 is zero
    wload<8>(wk,     (const float4*)kern + (size_t)kbc * 32 + jqc,        32);
    wload<8>(wk + 8, (const float4*)kern + (size_t)(64 + kbc) * 32 + jqc, 32);
    __syncthreads();

#pragma unroll 1
    for (int t = 0; t < T; t++) {
        // ---- step head ----
        if (tid < 128) {
            sx[r][c] = emb[(size_t)snidx[r] * 64 + c];
            sxl[r][c] = rpop;
        }
        oskip0.x = oskip0.y = oskip0.z = oskip0.w = 0.f;
        oskip1.x = oskip1.y = oskip1.z = oskip1.w = 0.f;
        __syncthreads();

#pragma unroll 1
        for (int i = 0; i < NLAYER; i++) {
            const int d = 1 << (i % 10);
            const long long off = (long long)(i / 10) * 1023 + (d - 1);

            // ---- Phase A: conv FMA (FULLY prefetched, zero exposed LDG)
            //      + ring push + wr prefetch ----
            {
                float4 o0 = {0,0,0,0}, o1 = {0,0,0,0};
                mm_reg<8>(sxl[0] + kbc, sxl[1] + kbc, wk,     o0, o1);
                mm_reg<8>(sx[0] + kbc,  sx[1] + kbc,  wk + 8, o0, o1);
                *(float4*)&scp[ksc][0][4 * jqc] = o0;
                *(float4*)&scp[ksc][1][4 * jqc] = o1;
            }
            if (tid < 128) {
                size_t idx = ((size_t)(row0 + r) * RING_PER_ROW + (size_t)off
                              + (t & (d - 1))) * 64 + c;
                g_ring[idx] = sx[r][c];
            }
            wload<4>(wr, (const float4*)rw + (size_t)i * 64 * 16
                         + (size_t)kbr * 16 + jqr, 16);
            __syncthreads();

            // ---- Phase B: gate + next conv (or head W0) full prefetch + pop ----
            if (i < NLAYER - 1) {
                const float4* KN = (const float4*)kern + (size_t)((i + 1) * 2) * 64 * 32;
                wload<8>(wk,     KN + (size_t)kbc * 32 + jqc,        32);
                wload<8>(wk + 8, KN + (size_t)(64 + kbc) * 32 + jqc, 32);
                if (tid < 128) {
                    const int d2 = 1 << ((i + 1) % 10);
                    const long long off2 = (long long)((i + 1) / 10) * 1023 + (d2 - 1);
                    size_t idx2 = ((size_t)(row0 + r) * RING_PER_ROW + (size_t)off2
                                   + (t & (d2 - 1))) * 64 + c;
                    rpop = (t >= d2) ? g_ring[idx2] : 0.f;
                }
            } else {
                wload<8>(wk,     (const float4*)ow0 + (size_t)kbh * 64 + jqh,       64);
                wload<8>(wk + 8, (const float4*)ow0 + (size_t)(kbh + 8) * 64 + jqh, 64);
            }
            if (tid < 128) {
                float p0 = scp[0][r][c], p1 = scp[1][r][c];
                float p2 = scp[2][r][c], p3 = scp[3][r][c];
                float p4 = scp[4][r][c], p5 = scp[5][r][c];
                float p6 = scp[6][r][c], p7 = scp[7][r][c];
                float q0 = scp[0][r][c+64], q1 = scp[1][r][c+64];
                float q2 = scp[2][r][c+64], q3 = scp[3][r][c+64];
                float q4 = scp[4][r][c+64], q5 = scp[5][r][c+64];
                float q6 = scp[6][r][c+64], q7 = scp[7][r][c+64];
                float ht = (((p0+p1)+(p2+p3)) + ((p4+p5)+(p6+p7))) + cbs[i*128 + c];
                float hs = (((q0+q1)+(q2+q3)) + ((q4+q5)+(q6+q7))) + cbs[i*128 + 64 + c];
                float e2 = __expf(2.f * ht);
                float th = 1.f - __fdividef(2.f, e2 + 1.f);
                float sig = __fdividef(1.f, 1.f + __expf(-hs));
                sg[r][c] = th * sig;
            }
            __syncthreads();

            // ---- Phase C: res FMA (prefetched) + skip FMA (fully streamed;
            //      freed registers let ptxas batch the LDGs up front) ----
            {
                float4 o0 = {0,0,0,0}, o1 = {0,0,0,0};
                mm_reg<4>(sg[0] + kbr, sg[1] + kbr, wr, o0, o1);
                *(float4*)&srp[ksr][0][4 * jqr] = o0;
                *(float4*)&srp[ksr][1][4 * jqr] = o1;
            }
            {
                const float4* SW = (const float4*)sw + (size_t)i * 64 * 64
                                   + (size_t)kbs * 64 + jqs;
                mm_gl<16>(sg[0] + kbs, sg[1] + kbs, SW, 64, oskip0, oskip1);
            }
            __syncthreads();

            // ---- Phase D: x combine (tree-16) + stage next sxl ----
            if (tid < 128) {
                float a0 = srp[0][r][c] + srp[1][r][c];
                float a1 = srp[2][r][c] + srp[3][r][c];
                float a2 = srp[4][r][c] + srp[5][r][c];
                float a3 = srp[6][r][c] + srp[7][r][c];
                float a4 = srp[8][r][c] + srp[9][r][c];
                float a5 = srp[10][r][c] + srp[11][r][c];
                float a6 = srp[12][r][c] + srp[13][r][c];
                float a7 = srp[14][r][c] + srp[15][r][c];
                float v = sx[r][c] + rbs[i*64 + c]
                        + (((a0+a1)+(a2+a3)) + ((a4+a5)+(a6+a7)));
                sx[r][c] = v;
                if (i < NLAYER - 1) sxl[r][c] = rpop;
            }
            __syncthreads();
        }

        // ---- skip finalize: STS register partials ----
        *(float4*)&ssp[kss][0][4 * jqs] = oskip0;
        *(float4*)&ssp[kss][1][4 * jqs] = oskip1;
        __syncthreads();
        // combine + Σbias + relu (256 threads x 2 rows)
        {
            float v0 = ssb[ch] + ((ssp[0][0][ch] + ssp[1][0][ch])
                                + (ssp[2][0][ch] + ssp[3][0][ch]));
            float v1 = ssb[ch] + ((ssp[0][1][ch] + ssp[1][1][ch])
                                + (ssp[2][1][ch] + ssp[3][1][ch]));
            ssk[0][ch] = fmaxf(v0, 0.f);
            ssk[1][ch] = fmaxf(v1, 0.f);
        }
        __syncthreads();

        // ---- head m0: h0 = relu(skip @ ow0 + ob0), 16 pre + 48 stream ----
        {
            const float4* W = (const float4*)ow0 + (size_t)kbh * 64 + jqh;
            float4 o0 = {0,0,0,0}, o1 = {0,0,0,0};
            mm_reg<16>(ssk[0] + kbh,      ssk[1] + kbh,      wk, o0, o1);
            mm_gl<48>(ssk[0] + kbh + 16, ssk[1] + kbh + 16, W + 16 * 64, 64, o0, o1);
            wload<8>(wk,     (const float4*)ow1 + (size_t)kbh * 64 + jqh,       64);
            wload<8>(wk + 8, (const float4*)ow1 + (size_t)(kbh + 8) * 64 + jqh, 64);
            *(float4*)&ssp[ksh][0][4 * jqh] = o0;
            *(float4*)&ssp[ksh][1][4 * jqh] = o1;
        }
        __syncthreads();
        {
            float v0 = obs0[ch] + ((ssp[0][0][ch] + ssp[1][0][ch])
                                 + (ssp[2][0][ch] + ssp[3][0][ch]));
            float v1 = obs0[ch] + ((ssp[0][1][ch] + ssp[1][1][ch])
                                 + (ssp[2][1][ch] + ssp[3][1][ch]));
            sh0[0][ch] = fmaxf(v0, 0.f);
            sh0[1][ch] = fmaxf(v1, 0.f);
        }
        __syncthreads();

        // ---- head m1: logits = h0 @ ow1 + ob1 ----
        {
            const float4* W = (const float4*)ow1 + (size_t)kbh * 64 + jqh;
            float4 o0 = {0,0,0,0}, o1 = {0,0,0,0};
            mm_reg<16>(sh0[0] + kbh,      sh0[1] + kbh,      wk, o0, o1);
            mm_gl<48>(sh0[0] + kbh + 16, sh0[1] + kbh + 16, W + 16 * 64, 64, o0, o1);
            // prefetch (t+1, layer 0) conv weights + layer-0 pop
            wload<8>(wk,     (const float4*)kern + (size_t)kbc * 32 + jqc,        32);
            wload<8>(wk + 8, (const float4*)kern + (size_t)(64 + kbc) * 32 + jqc, 32);
            if (tid < 128)
                rpop = g_ring[((size_t)(row0 + r) * RING_PER_ROW) * 64 + c];
            *(float4*)&ssp[ksh][0][4 * jqh] = o0;
            *(float4*)&ssp[ksh][1][4 * jqh] = o1;
        }
        __syncthreads();
        {
            float v0 = obs1[ch] + ((ssp[0][0][ch] + ssp[1][0][ch])
                                 + (ssp[2][0][ch] + ssp[3][0][ch]));
            float v1 = obs1[ch] + ((ssp[0][1][ch] + ssp[1][1][ch])
                                 + (ssp[2][1][ch] + ssp[3][1][ch]));
            slg[0][ch] = v0;
            slg[1][ch] = v1;
            if (mode & 2) {
                out[logit_off + ((size_t)(row0 + 0) * T + t) * VV + ch] = v0;
                out[logit_off + ((size_t)(row0 + 1) * T + t) * VV + ch] = v1;
            }
        }
        __syncthreads();

        // ---- argmax per row (first-max tie rule, matches jnp.argmax) ----
        if (tid < 64) {
            int rr = tid >> 5, lane = tid & 31;
            float bv = -FLT_MAX;
            int bi = 0;
#pragma unroll
            for (int jj = 0; jj < 8; jj++) {
                int j = lane + jj * 32;
                float v = slg[rr][j];
                if (v > bv) { bv = v; bi = j; }
            }
#pragma unroll
            for (int o2 = 16; o2 > 0; o2 >>= 1) {
                float ov = __shfl_down_sync(0xffffffffu, bv, o2);
                int   oi = __shfl_down_sync(0xffffffffu, bi, o2);
                if (ov > bv || (ov == bv && oi < bi)) { bv = ov; bi = oi; }
            }
            if (lane == 0) {
                snidx[rr] = bi;
                if (mode & 1) out[samp_off + (size_t)(row0 + rr) * T + t] = (float)bi;
                if (mode & 4) ((int*)out)[(size_t)(row0 + rr) * T + t] = bi;
            }
        }
        __syncthreads();
    }
}

extern "C" void kernel_launch(void* const* d_in, const int* in_sizes, int n_in,
                              void* d_out, int out_size) {
    const int*   seed  = (const int*)d_in[0];
    const float* emb   = (const float*)d_in[1];
    const float* kern  = (const float*)d_in[2];
    const float* cbias = (const float*)d_in[3];
    const float* rw    = (const float*)d_in[4];
    const float* rb    = (const float*)d_in[5];
    const float* sw    = (const float*)d_in[6];
    const float* sb    = (const float*)d_in[7];
    const float* ow0   = (const float*)d_in[8];
    const float* ob0   = (const float*)d_in[9];
    const float* ow1   = (const float*)d_in[10];
    const float* ob1   = (const float*)d_in[11];
    (void)in_sizes; (void)n_in;

    int T, mode;
    long long samp_off = 0, logit_off = 0;
    if (out_size % (BB * (VV + 1)) == 0) {
        T = out_size / (BB * (VV + 1));
        mode = 1 | 2;                       // float samples then logits
        samp_off = 0;
        logit_off = (long long)BB * T;
    } else if (out_size % (BB * VV) == 0) {
        T = out_size / (BB * VV);
        mode = 2;                           // logits only
        logit_off = 0;
    } else {
        T = out_size / BB;
        mode = 4;                           // int32 samples only
    }

    wavenet_kernel<<<BB / 2, 256>>>(seed, emb, kern, cbias, rw, rb, sw, sb,
                                    ow0, ob0, ow1, ob1,
                                    (float*)d_out, T, samp_off, logit_off, mode);
}

// round 11
// speedup vs baseline: 1.2043x; 1.1102x over previous
#include <cuda_runtime.h>
#include <math.h>
#include <float.h>

// WaveNet autoregressive generation, sm_103a — round 10: warp specialization.
// 64 CTAs x 2 rows. 384 threads = 256 "main" (R6's proven conv/gate/res
// mappings, skip work removed) + 128 "skip" threads that consume the gate
// output one layer behind (double-buffered sg) and accumulate the skip matmul
// in their own registers. Heterogeneous warps per scheduler let the skip
// LDG/FMA stream fill main's stall slots. One __syncthreads per layer is the
// only cross-group sync; main's internal syncs are named bar.sync 1,256.

#define NLAYER 30
#define BB 128
#define VV 256
#define RING_PER_ROW 3069   // 3 * (2^10 - 1) slots, 64 floats each

__device__ float g_ring[(size_t)BB * RING_PER_ROW * 64];  // ~100.6 MB scratch

#define BAR_MAIN() asm volatile("bar.sync 1, 256;" ::: "memory")

template<int N>
__device__ __forceinline__ void wload(float4* dst, const float4* __restrict__ Wg,
                                      int s4) {
#pragma unroll
    for (int u = 0; u < N; u++) dst[u] = Wg[(size_t)u * s4];
}

// FMA N k-steps (N%4==0), both rows, weights from a register buffer.
template<int N>
__device__ __forceinline__ void mm_reg(const float* __restrict__ a0,
                                       const float* __restrict__ a1,
                                       const float4* w, float4& o0, float4& o1) {
#pragma unroll
    for (int c2 = 0; c2 < N; c2 += 4) {
        float v0[4], v1[4];
        *(float4*)v0 = *(const float4*)(a0 + c2);
        *(float4*)v1 = *(const float4*)(a1 + c2);
#pragma unroll
        for (int u = 0; u < 4; u++) {
            const float4 wv = w[c2 + u];
            o0.x = fmaf(v0[u], wv.x, o0.x);
            o0.y = fmaf(v0[u], wv.y, o0.y);
            o0.z = fmaf(v0[u], wv.z, o0.z);
            o0.w = fmaf(v0[u], wv.w, o0.w);
            o1.x = fmaf(v1[u], wv.x, o1.x);
            o1.y = fmaf(v1[u], wv.y, o1.y);
            o1.z = fmaf(v1[u], wv.z, o1.z);
            o1.w = fmaf(v1[u], wv.w, o1.w);
        }
    }
}

// FMA N k-steps streaming weights from global (independent LDGs pipeline).
template<int N>
__device__ __forceinline__ void mm_gl(const float* __restrict__ a0,
                                      const float* __restrict__ a1,
                                      const float4* __restrict__ Wg, int s4,
                                      float4& o0, float4& o1) {
#pragma unroll
    for (int c2 = 0; c2 < N; c2 += 4) {
        float v0[4], v1[4];
        *(float4*)v0 = *(const float4*)(a0 + c2);
        *(float4*)v1 = *(const float4*)(a1 + c2);
#pragma unroll
        for (int u = 0; u < 4; u++) {
            const float4 wv = Wg[(size_t)(c2 + u) * s4];
            o0.x = fmaf(v0[u], wv.x, o0.x);
            o0.y = fmaf(v0[u], wv.y, o0.y);
            o0.z = fmaf(v0[u], wv.z, o0.z);
            o0.w = fmaf(v0[u], wv.w, o0.w);
            o1.x = fmaf(v1[u], wv.x, o1.x);
            o1.y = fmaf(v1[u], wv.y, o1.y);
            o1.z = fmaf(v1[u], wv.z, o1.z);
            o1.w = fmaf(v1[u], wv.w, o1.w);
        }
    }
}

__global__ __launch_bounds__(384, 1)
void wavenet_kernel(const int* __restrict__ seed,
                    const float* __restrict__ emb,     // (V, 64)
                    const float* __restrict__ kern,    // (L, 2, 64, 128)
                    const float* __restrict__ cbias,   // (L, 128)
                    const float* __restrict__ rw,      // (L, 64, 64)
                    const float* __restrict__ rb,      // (L, 64)
                    const float* __restrict__ sw,      // (L, 64, 256)
                    const float* __restrict__ sb,      // (L, 256)
                    const float* __restrict__ ow0,     // (256, 256)
                    const float* __restrict__ ob0,     // (256)
                    const float* __restrict__ ow1,     // (256, 256)
                    const float* __restrict__ ob1,     // (256)
                    float* __restrict__ out,
                    int T, long long samp_off, long long logit_off, int mode)
{
    __shared__ __align__(16) float sx[2][64];
    __shared__ __align__(16) float sxl[2][64];
    __shared__ __align__(16) float sgb[2][2][64];       // double-buffered gate
    __shared__ __align__(16) float ssk[2][256];
    __shared__ __align__(16) float sh0[2][256];
    __shared__ __align__(16) float slg[2][256];
    __shared__ __align__(16) float cbs[NLAYER * 128];   // staged conv bias
    __shared__ __align__(16) float rbs[NLAYER * 64];    // staged res bias
    __shared__ __align__(16) float ssb[256];            // sum of skip biases
    __shared__ __align__(16) float obs0[256], obs1[256];
    __shared__ __align__(16) float pbuf[3072];          // 12KB partials union
    __shared__ int snidx[2];

    float (*scp)[2][128] = (float(*)[2][128])pbuf;   // [8][2][128] conv
    float (*srp)[2][64]  = (float(*)[2][64])pbuf;    // [16][2][64] res
    float (*ssp)[2][256] = (float(*)[2][256])pbuf;   // [6][2][256] skip/head

    const int tid = threadIdx.x;
    const int row0 = blockIdx.x * 2;
    const bool is_main = tid < 256;

    // main mappings (identical to R6)
    const int jqc = tid & 31, ksc = tid >> 5, kbc = ksc * 8;   // conv 32jq x 8ks
    const int jqr = tid & 15, ksr = tid >> 4, kbr = ksr * 4;   // res  16jq x 16ks
    const int r = tid >> 6, c = tid & 63;                      // tid<128 combines
    const int ch = tid;                                        // tid<256 combines
    // head mapping over ALL 384 threads: 64jq x 6ks, k = {48,48,48,48,32,32}
    const int jqh = tid & 63, ksh = tid >> 6;
    const int khb = (ksh < 4) ? ksh * 48 : 192 + (ksh - 4) * 32;
    // skip-group mapping (tid >= 256): 64jq x 2ks of 32
    const int st = tid & 127;
    const int jqs = st & 63, kss = st >> 6, kbs = kss * 32;

    float4 wk[8];   // main: conv K0[0..3]|K1[4..7]; all: head rows khb..khb+7
    float4 wr[4];   // main: res prefetch
    float4 osk0 = {0,0,0,0}, osk1 = {0,0,0,0};  // skip-group accumulators
    float  rpop = 0.f;

    // ---- one-time staging ----
    for (int idx = tid; idx < NLAYER * 128; idx += 384) cbs[idx] = cbias[idx];
    for (int idx = tid; idx < NLAYER * 64;  idx += 384) rbs[idx] = rb[idx];
    if (tid < 256) {
        float s = 0.f;
#pragma unroll 1
        for (int i = 0; i < NLAYER; i++) s += sb[i * 256 + tid];
        ssb[tid] = s;
        obs0[tid] = ob0[tid];
        obs1[tid] = ob1[tid];
    }
    if (tid < 2) snidx[tid] = seed[row0 + tid];
    if (is_main) {   // prefetch conv (t=0, layer 0)
        wload<4>(wk,     (const float4*)kern + (size_t)kbc * 32 + jqc,        32);
        wload<4>(wk + 4, (const float4*)kern + (size_t)(64 + kbc) * 32 + jqc, 32);
    }
    __syncthreads();

#pragma unroll 1
    for (int t = 0; t < T; t++) {
        // ---- step head ----
        if (tid < 128) {
            sx[r][c] = emb[(size_t)snidx[r] * 64 + c];
            sxl[r][c] = rpop;
        }
        if (!is_main) {
            osk0.x = osk0.y = osk0.z = osk0.w = 0.f;
            osk1.x = osk1.y = osk1.z = osk1.w = 0.f;
        }

#pragma unroll 1
        for (int i = 0; i < NLAYER; i++) {
            __syncthreads();   // P_i: sx_i ready; sg[i-1] ready; skip_{i-2} done

            if (is_main) {
                const int d = 1 << (i % 10);
                const long long off = (long long)(i / 10) * 1023 + (d - 1);

                // -- A: conv partials (4 pre + 4 stream per matrix) + push + wr
                {
                    const float4* K0 = (const float4*)kern
                        + (size_t)(i * 2) * 64 * 32 + (size_t)kbc * 32 + jqc;
                    const float4* K1 = K0 + 64 * 32;
                    float4 o0 = {0,0,0,0}, o1 = {0,0,0,0};
                    mm_reg<4>(sxl[0] + kbc,     sxl[1] + kbc,     wk,     o0, o1);
                    mm_gl<4> (sxl[0] + kbc + 4, sxl[1] + kbc + 4, K0 + 4*32, 32, o0, o1);
                    mm_reg<4>(sx[0] + kbc,      sx[1] + kbc,      wk + 4, o0, o1);
                    mm_gl<4> (sx[0] + kbc + 4,  sx[1] + kbc + 4,  K1 + 4*32, 32, o0, o1);
                    *(float4*)&scp[ksc][0][4 * jqc] = o0;
                    *(float4*)&scp[ksc][1][4 * jqc] = o1;
                }
                if (tid < 128) {
                    size_t idx = ((size_t)(row0 + r) * RING_PER_ROW + (size_t)off
                                  + (t & (d - 1))) * 64 + c;
                    g_ring[idx] = sx[r][c];
                }
                wload<4>(wr, (const float4*)rw + (size_t)i * 64 * 16
                             + (size_t)kbr * 16 + jqr, 16);
                BAR_MAIN();

                // -- B: gate -> sg[i&1]; prefetch next conv + next pop
                if (i < NLAYER - 1) {
                    const float4* KN = (const float4*)kern
                        + (size_t)((i + 1) * 2) * 64 * 32;
                    wload<4>(wk,     KN + (size_t)kbc * 32 + jqc,        32);
                    wload<4>(wk + 4, KN + (size_t)(64 + kbc) * 32 + jqc, 32);
                    if (tid < 128) {
                        const int d2 = 1 << ((i + 1) % 10);
                        const long long off2 = (long long)((i + 1) / 10) * 1023 + (d2 - 1);
                        size_t idx2 = ((size_t)(row0 + r) * RING_PER_ROW + (size_t)off2
                                       + (t & (d2 - 1))) * 64 + c;
                        rpop = (t >= d2) ? g_ring[idx2] : 0.f;
                    }
                }
                if (tid < 128) {
                    float p0 = scp[0][r][c], p1 = scp[1][r][c];
                    float p2 = scp[2][r][c], p3 = scp[3][r][c];
                    float p4 = scp[4][r][c], p5 = scp[5][r][c];
                    float p6 = scp[6][r][c], p7 = scp[7][r][c];
                    float q0 = scp[0][r][c+64], q1 = scp[1][r][c+64];
                    float q2 = scp[2][r][c+64], q3 = scp[3][r][c+64];
                    float q4 = scp[4][r][c+64], q5 = scp[5][r][c+64];
                    float q6 = scp[6][r][c+64], q7 = scp[7][r][c+64];
                    float ht = (((p0+p1)+(p2+p3)) + ((p4+p5)+(p6+p7))) + cbs[i*128 + c];
                    float hs = (((q0+q1)+(q2+q3)) + ((q4+q5)+(q6+q7))) + cbs[i*128 + 64 + c];
                    float e2 = __expf(2.f * ht);
                    float th = 1.f - __fdividef(2.f, e2 + 1.f);
                    float sig = __fdividef(1.f, 1.f + __expf(-hs));
                    sgb[i & 1][r][c] = th * sig;
                }
                BAR_MAIN();

                // -- C: res partials (fully prefetched)
                {
                    float4 o0 = {0,0,0,0}, o1 = {0,0,0,0};
                    mm_reg<4>(sgb[i & 1][0] + kbr, sgb[i & 1][1] + kbr, wr, o0, o1);
                    *(float4*)&srp[ksr][0][4 * jqr] = o0;
                    *(float4*)&srp[ksr][1][4 * jqr] = o1;
                }
                BAR_MAIN();

                // -- D: x combine (tree-16) + stage next sxl
                if (tid < 128) {
                    float a0 = srp[0][r][c] + srp[1][r][c];
                    float a1 = srp[2][r][c] + srp[3][r][c];
                    float a2 = srp[4][r][c] + srp[5][r][c];
                    float a3 = srp[6][r][c] + srp[7][r][c];
                    float a4 = srp[8][r][c] + srp[9][r][c];
                    float a5 = srp[10][r][c] + srp[11][r][c];
                    float a6 = srp[12][r][c] + srp[13][r][c];
                    float a7 = srp[14][r][c] + srp[15][r][c];
                    float v = sx[r][c] + rbs[i*64 + c]
                            + (((a0+a1)+(a2+a3)) + ((a4+a5)+(a6+a7)));
                    sx[r][c] = v;
                    if (i < NLAYER - 1) sxl[r][c] = rpop;
                }
            } else {
                // ---- skip group: skip matmul of layer i-1 (reads sg[(i-1)&1],
                //      which main is not writing this iteration) ----
                if (i > 0) {
                    const float4* SW = (const float4*)sw
                        + ((size_t)(i - 1) * 64 + kbs) * 64 + jqs;
                    mm_gl<32>(sgb[(i - 1) & 1][0] + kbs, sgb[(i - 1) & 1][1] + kbs,
                              SW, 64, osk0, osk1);
                }
            }
        }
        __syncthreads();   // P_30: layer 29 gate + combine done

        // ---- tail: skip_29 (skip group) while everyone prefetches head W0 ----
        wload<8>(wk, (const float4*)ow0 + (size_t)khb * 64 + jqh, 64);
        if (!is_main) {
            const float4* SW = (const float4*)sw
                + ((size_t)(NLAYER - 1) * 64 + kbs) * 64 + jqs;
            mm_gl<32>(sgb[(NLAYER - 1) & 1][0] + kbs, sgb[(NLAYER - 1) & 1][1] + kbs,
                      SW, 64, osk0, osk1);
            *(float4*)&ssp[kss][0][4 * jqs] = osk0;
            *(float4*)&ssp[kss][1][4 * jqs] = osk1;
        }
        __syncthreads();

        // ---- skip combine + Σbias + relu ----
        if (is_main) {
            float v0 = ssb[ch] + ssp[0][0][ch] + ssp[1][0][ch];
            float v1 = ssb[ch] + ssp[0][1][ch] + ssp[1][1][ch];
            ssk[0][ch] = fmaxf(v0, 0.f);
            ssk[1][ch] = fmaxf(v1, 0.f);
        }
        __syncthreads();

        // ---- head m0: h0 = relu(skip @ ow0 + ob0); all 384 threads ----
        {
            const float4* W = (const float4*)ow0 + (size_t)khb * 64 + jqh;
            float4 o0 = {0,0,0,0}, o1 = {0,0,0,0};
            mm_reg<8>(ssk[0] + khb, ssk[1] + khb, wk, o0, o1);
            if (ksh < 4)
                mm_gl<40>(ssk[0] + khb + 8, ssk[1] + khb + 8, W + 8*64, 64, o0, o1);
            else
                mm_gl<24>(ssk[0] + khb + 8, ssk[1] + khb + 8, W + 8*64, 64, o0, o1);
            wload<8>(wk, (const float4*)ow1 + (size_t)khb * 64 + jqh, 64);
            *(float4*)&ssp[ksh][0][4 * jqh] = o0;
            *(float4*)&ssp[ksh][1][4 * jqh] = o1;
        }
        __syncthreads();
        if (is_main) {
            float v0 = obs0[ch] + (((ssp[0][0][ch] + ssp[1][0][ch])
                                  + (ssp[2][0][ch] + ssp[3][0][ch]))
                                  + (ssp[4][0][ch] + ssp[5][0][ch]));
            float v1 = obs0[ch] + (((ssp[0][1][ch] + ssp[1][1][ch])
                                  + (ssp[2][1][ch] + ssp[3][1][ch]))
                                  + (ssp[4][1][ch] + ssp[5][1][ch]));
            sh0[0][ch] = fmaxf(v0, 0.f);
            sh0[1][ch] = fmaxf(v1, 0.f);
        }
        __syncthreads();

        // ---- head m1: logits = h0 @ ow1 + ob1; all 384 threads ----
        {
            const float4* W = (const float4*)ow1 + (size_t)khb * 64 + jqh;
            float4 o0 = {0,0,0,0}, o1 = {0,0,0,0};
            mm_reg<8>(sh0[0] + khb, sh0[1] + khb, wk, o0, o1);
            if (ksh < 4)
                mm_gl<40>(sh0[0] + khb + 8, sh0[1] + khb + 8, W + 8*64, 64, o0, o1);
            else
                mm_gl<24>(sh0[0] + khb + 8, sh0[1] + khb + 8, W + 8*64, 64, o0, o1);
            // prefetch (t+1, layer 0) conv weights + layer-0 pop
            if (is_main) {
                wload<4>(wk,     (const float4*)kern + (size_t)kbc * 32 + jqc,        32);
                wload<4>(wk + 4, (const float4*)kern + (size_t)(64 + kbc) * 32 + jqc, 32);
            }
            if (tid < 128)
                rpop = g_ring[((size_t)(row0 + r) * RING_PER_ROW) * 64 + c];
            *(float4*)&ssp[ksh][0][4 * jqh] = o0;
            *(float4*)&ssp[ksh][1][4 * jqh] = o1;
        }
        __syncthreads();
        if (is_main) {
            float v0 = obs1[ch] + (((ssp[0][0][ch] + ssp[1][0][ch])
                                  + (ssp[2][0][ch] + ssp[3][0][ch]))
                                  + (ssp[4][0][ch] + ssp[5][0][ch]));
            float v1 = obs1[ch] + (((ssp[0][1][ch] + ssp[1][1][ch])
                                  + (ssp[2][1][ch] + ssp[3][1][ch]))
                                  + (ssp[4][1][ch] + ssp[5][1][ch]));
            slg[0][ch] = v0;
            slg[1][ch] = v1;
            if (mode & 2) {
                out[logit_off + ((size_t)(row0 + 0) * T + t) * VV + ch] = v0;
                out[logit_off + ((size_t)(row0 + 1) * T + t) * VV + ch] = v1;
            }
        }
        __syncthreads();

        // ---- argmax per row (first-max tie rule, matches jnp.argmax) ----
        if (tid < 64) {
            int rr = tid >> 5, lane = tid & 31;
            float bv = -FLT_MAX;
            int bi = 0;
#pragma unroll
            for (int jj = 0; jj < 8; jj++) {
                int j = lane + jj * 32;
                float v = slg[rr][j];
                if (v > bv) { bv = v; bi = j; }
            }
#pragma unroll
            for (int o2 = 16; o2 > 0; o2 >>= 1) {
                float ov = __shfl_down_sync(0xffffffffu, bv, o2);
                int   oi = __shfl_down_sync(0xffffffffu, bi, o2);
                if (ov > bv || (ov == bv && oi < bi)) { bv = ov; bi = oi; }
            }
            if (lane == 0) {
                snidx[rr] = bi;
                if (mode & 1) out[samp_off + (size_t)(row0 + rr) * T + t] = (float)bi;
                if (mode & 4) ((int*)out)[(size_t)(row0 + rr) * T + t] = bi;
            }
        }
        __syncthreads();
    }
}

extern "C" void kernel_launch(void* const* d_in, const int* in_sizes, int n_in,
                              void* d_out, int out_size) {
    const int*   seed  = (const int*)d_in[0];
    const float* emb   = (const float*)d_in[1];
    const float* kern  = (const float*)d_in[2];
    const float* cbias = (const float*)d_in[3];
    const float* rw    = (const float*)d_in[4];
    const float* rb    = (const float*)d_in[5];
    const float* sw    = (const float*)d_in[6];
    const float* sb    = (const float*)d_in[7];
    const float* ow0   = (const float*)d_in[8];
    const float* ob0   = (const float*)d_in[9];
    const float* ow1   = (const float*)d_in[10];
    const float* ob1   = (const float*)d_in[11];
    (void)in_sizes; (void)n_in;

    int T, mode;
    long long samp_off = 0, logit_off = 0;
    if (out_size % (BB * (VV + 1)) == 0) {
        T = out_size / (BB * (VV + 1));
        mode = 1 | 2;                       // float samples then logits
        samp_off = 0;
        logit_off = (long long)BB * T;
    } else if (out_size % (BB * VV) == 0) {
        T = out_size / (BB * VV);
        mode = 2;                           // logits only
        logit_off = 0;
    } else {
        T = out_size / BB;
        mode = 4;                           // int32 samples only
    }

    wavenet_kernel<<<BB / 2, 384>>>(seed, emb, kern, cbias, rw, rb, sw, sb,
                                    ow0, ob0, ow1, ob1,
                                    (float*)d_out, T, samp_off, logit_off, mode);
}